// round 12
// baseline (speedup 1.0000x reference)
#include <cuda_runtime.h>
#include <cuda_fp16.h>
#include <cstdint>

#define BH   16
#define T_   2048
#define N_   1024
#define D_   128
#define TM   128          // t-rows per CTA tile
#define TSN  128          // s-cols per CTA tile
#define KC   128          // k-chunk (fp16 elems)
#define NCH  8            // N_/KC
#define NTT  16           // T_/TM
#define NTH  512          // attention kernel threads (16 warps)
#define PTH  256          // prep kernel threads

#define NB_ROPE 32768     // rope part: BH*T_*(N_/4) / 256
#define NB_VT   4096      // vt part:   (T_/32)*(D_/32)*BH

// ---------------- global scratch (static device alloc — allowed) ----------
__device__ __half g_QH[(size_t)BH * T_ * N_];   // 64 MiB (RoPE'd Q, fp16)
__device__ __half g_VTH[(size_t)BH * D_ * T_];  //  8 MiB (V^T, fp16)

// ---------------- helpers --------------------------------------------------
__device__ __forceinline__ uint32_t smem_u32(const void* p) {
    uint32_t a;
    asm("{ .reg .u64 t; cvta.to.shared.u64 t, %1; cvt.u32.u64 %0, t; }"
        : "=r"(a) : "l"(p));
    return a;
}
__device__ __forceinline__ uint32_t swz(uint32_t off) {   // SW128 swizzle
    return off ^ ((off >> 3) & 0x70);
}
__device__ __forceinline__ void cp16(uint32_t sdst, const void* g) {
    asm volatile("cp.async.cg.shared.global [%0], [%1], 16;\n"
                 :: "r"(sdst), "l"(g) : "memory");
}
#define CP_COMMIT() asm volatile("cp.async.commit_group;\n" ::: "memory")
#define CP_WAIT0()  asm volatile("cp.async.wait_group 0;\n" ::: "memory")

__device__ __forceinline__ void ldsm4(uint32_t& r0, uint32_t& r1,
                                      uint32_t& r2, uint32_t& r3, uint32_t a) {
    asm volatile("ldmatrix.sync.aligned.m8n8.x4.shared.b16 {%0,%1,%2,%3}, [%4];"
                 : "=r"(r0), "=r"(r1), "=r"(r2), "=r"(r3) : "r"(a));
}
__device__ __forceinline__ void mma_fp16(float c[4],
        uint32_t a0, uint32_t a1, uint32_t a2, uint32_t a3,
        uint32_t b0, uint32_t b1) {
    asm volatile(
        "mma.sync.aligned.m16n8k16.row.col.f32.f16.f16.f32 "
        "{%0,%1,%2,%3}, {%4,%5,%6,%7}, {%8,%9}, {%0,%1,%2,%3};"
        : "+f"(c[0]), "+f"(c[1]), "+f"(c[2]), "+f"(c[3])
        : "r"(a0), "r"(a1), "r"(a2), "r"(a3), "r"(b0), "r"(b1));
}
__device__ __forceinline__ void sts32(uint32_t addr, uint32_t v) {
    asm volatile("st.shared.b32 [%0], %1;" :: "r"(addr), "r"(v) : "memory");
}
__device__ __forceinline__ uint32_t pack_h2(float lo, float hi) {
    __half2 h = __floats2half2_rn(lo, hi);
    return *reinterpret_cast<uint32_t*>(&h);
}

// ---------------- merged prep: RoPE (rope blocks) + V^T (vt blocks) -------
__global__ void prep_kernel(const float* __restrict__ Q,
                            const float* __restrict__ V) {
    __shared__ float tile[32][33];
    const uint32_t bid = blockIdx.x;
    const int tid = threadIdx.x;

    if (bid < NB_ROPE) {
        // ---- RoPE + fp16 quantize, 2 pairs (1 float4) per thread ----
        uint32_t i4 = bid * PTH + tid;
        uint32_t p0 = 2u * i4;                 // first pair index
        uint32_t n2 = p0 & 511u;               // N_/2 = 512 pairs per row
        uint32_t t  = (p0 >> 9) & 2047u;

        const float4 q = ((const float4*)Q)[i4];
        float tf = (float)t;

        float pos0 = (float)(2u * n2);
        float f0 = exp2f(-16.0f * pos0 * (1.0f / (float)N_)) * 0.15915494309189535f;
        float r0 = tf * f0;
        float ph0 = (r0 - floorf(r0)) * 6.283185307179586f;
        float s0, c0; __sincosf(ph0, &s0, &c0);

        float pos1 = (float)(2u * (n2 + 1u));
        float f1 = exp2f(-16.0f * pos1 * (1.0f / (float)N_)) * 0.15915494309189535f;
        float r1 = tf * f1;
        float ph1 = (r1 - floorf(r1)) * 6.283185307179586f;
        float s1, c1; __sincosf(ph1, &s1, &c1);

        uint2 o;
        o.x = pack_h2(q.x * c0 - q.y * s0, q.y * c0 + q.x * s0);
        o.y = pack_h2(q.z * c1 - q.w * s1, q.w * c1 + q.z * s1);
        ((uint2*)g_QH)[i4] = o;
    } else {
        // ---- coalesced tiled V transpose + fp16 quantize ----
        const uint32_t vb = bid - NB_ROPE;
        const int t0 = (int)(vb & 63u) * 32;        // T_/32 = 64
        const int d0 = (int)((vb >> 6) & 3u) * 32;  // D_/32 = 4
        const int bh = (int)(vb >> 8);
        const int tx = tid & 31, ty = tid >> 5;     // (32, 8)

        const float* Vb = V + ((size_t)bh * T_) * D_;
#pragma unroll
        for (int i = 0; i < 4; ++i)
            tile[ty + i * 8][tx] = Vb[(size_t)(t0 + ty + i * 8) * D_ + d0 + tx];
        __syncthreads();

        __half* VTb = g_VTH + (size_t)bh * D_ * T_;
#pragma unroll
        for (int i = 0; i < 4; ++i)
            VTb[(size_t)(d0 + ty + i * 8) * T_ + t0 + tx] =
                __float2half(tile[tx][ty + i * 8]);
    }
}

// ---------------- attention (mma.sync fp16, 16 warps, split halves) -------
// smem map (bytes):
//   [0, 128K)    : Q chunk double buffer, buf b at b*65536:
//                  Qt_sub0(+0) Qt_sub1(+16K) Qs_sub0(+32K) Qs_sub1(+48K)
//                  each subtile [128 rows][64 k] fp16, SW128
//   [128K, 160K) : V tile: V_sub0(+0) V_sub1(+16K), [128 d][64 s] each
//   [160K, 192K) : S tile: S_sub0(+0) S_sub1(+16K), [128 t][64 s] each
#define SM_V   131072
#define SM_S   163840
#define SM_TOT 196608

__device__ __forceinline__ void load_q_chunk(
    uint32_t sb, int buf, int k0, int t0, int s0, int tid,
    const __half* QHb) {
    int tsel = tid >> 8;        // 0: Qt, 1: Qs
    int u    = tid & 255;
    const __half* src = QHb + (size_t)(tsel ? s0 : t0) * N_ + k0;
    uint32_t tb = sb + (uint32_t)buf * 65536u + (uint32_t)tsel * 32768u;
#pragma unroll
    for (int i = 0; i < 8; ++i) {
        int idx = u * 8 + i;               // 0..2047 (16B units), 16/row
        int r = idx >> 4, c16 = idx & 15;
        cp16(tb + (uint32_t)((c16 >> 3) * 16384) +
                 swz((uint32_t)(r * 128 + (c16 & 7) * 16)),
             src + (size_t)r * N_ + c16 * 8);
    }
}

__device__ __forceinline__ void load_v_tile(
    uint32_t sb, int s0, int tid, const __half* VHb) {
#pragma unroll
    for (int i = 0; i < 4; ++i) {
        int idx = tid * 4 + i;             // 0..2047 (16B units), 16/row
        int r = idx >> 4, c16 = idx & 15;
        cp16(sb + SM_V + (uint32_t)((c16 >> 3) * 16384) +
                 swz((uint32_t)(r * 128 + (c16 & 7) * 16)),
             VHb + (size_t)r * T_ + s0 + c16 * 8);
    }
}

__global__ void __launch_bounds__(NTH)
attn_mma_kernel(float* __restrict__ O) {
    extern __shared__ char smem[];
    uint32_t sb = smem_u32(smem);
    const int tid  = threadIdx.x;
    const int w    = tid >> 5;
    const int wr   = w & 7;           // row group: t-rows [16wr, 16wr+16)
    const int wc   = w >> 3;          // column half: cols [64wc, 64wc+64)
    const int lane = tid & 31;
    const int lrow = lane & 15;       // ldmatrix row-within-16
    const int lgrp = lane >> 4;       // ldmatrix 16B-column select
    const int qr   = lane >> 2;       // C/A-frag row within 8
    const int qc   = (lane & 3) << 1; // C/A-frag col pair

    const int bh = blockIdx.x / 9;
    const int c  = blockIdx.x % 9;

    int tts[2]; int nrep;
    if (c == 0)      { tts[0] = 15; tts[1] = 15; nrep = 1; }
    else if (c == 8) { tts[0] = 7;  tts[1] = 7;  nrep = 1; }
    else             { tts[0] = 15 - c; tts[1] = c - 1; nrep = 2; }

    const __half* QHb = g_QH  + (size_t)bh * T_ * N_;
    const __half* VHb = g_VTH + (size_t)bh * D_ * T_;
    float* Ob = O + (size_t)bh * T_ * D_;

    const int w16 = wr * 16;
    const int c64 = wc * 64;

    // prologue: chunk0 of first s-tile into buf0
    load_q_chunk(sb, 0, 0, tts[0] * TM, 0, tid, QHb);
    CP_COMMIT();

    for (int rep = 0; rep < nrep; ++rep) {
        const int tt = tts[rep];
        const int t0 = tt * TM;

        float Oacc[8][4];                 // 16 rows x 64 d (own half)
#pragma unroll
        for (int b = 0; b < 8; ++b)
#pragma unroll
            for (int x = 0; x < 4; ++x) Oacc[b][x] = 0.0f;

        for (int st = 0; st <= tt; ++st) {
            const int s0 = st * TSN;
            const bool diag = (st == tt);
            const bool wskip = diag && (c64 >= w16 + 16);

            float Sacc[8][4];             // 16 rows x 64 s (own half)
#pragma unroll
            for (int b = 0; b < 8; ++b)
#pragma unroll
                for (int x = 0; x < 4; ++x) Sacc[b][x] = 0.0f;

            // ---- stage 1: S = Qt @ Qs^T, 8 double-buffered K=128 chunks --
            for (int cc = 0; cc < NCH; ++cc) {
                CP_WAIT0();
                __syncthreads();
                // issue next loads AFTER the barrier (WAR-safe)
                if (cc + 1 < NCH) {
                    load_q_chunk(sb, (cc + 1) & 1, (cc + 1) * KC, t0, s0, tid, QHb);
                } else if (st < tt) {
                    load_q_chunk(sb, 0, 0, t0, s0 + TSN, tid, QHb);
                } else if (rep + 1 < nrep) {
                    load_q_chunk(sb, 0, 0, tts[rep + 1] * TM, 0, tid, QHb);
                }
                if (cc == 0) load_v_tile(sb, s0, tid, VHb);
                CP_COMMIT();

                if (!wskip) {
                    const uint32_t qb = sb + (uint32_t)(cc & 1) * 65536u;
#pragma unroll
                    for (int ks = 0; ks < 8; ++ks) {
                        const uint32_t qtb = qb + (uint32_t)((ks >> 2) * 16384);
                        const uint32_t qsb = qb + 32768u + (uint32_t)((ks >> 2) * 16384);
                        const int kb = (ks & 3) * 32 + lgrp * 16;
                        uint32_t a0, a1, a2, a3;
                        ldsm4(a0, a1, a2, a3,
                              qtb + swz((uint32_t)((w16 + lrow) * 128 + kb)));
#pragma unroll
                        for (int sg = 0; sg < 4; ++sg) {
                            if (diag && (c64 + sg * 16 >= w16 + 16)) continue;
                            uint32_t r0, r1, r2, r3;
                            ldsm4(r0, r1, r2, r3,
                                  qsb + swz((uint32_t)((c64 + sg * 16 + lrow) * 128 + kb)));
                            mma_fp16(Sacc[2 * sg],     a0, a1, a2, a3, r0, r2);
                            mma_fp16(Sacc[2 * sg + 1], a0, a1, a2, a3, r1, r3);
                        }
                    }
                }
            }

            // ---- mask + fp16-pack S, write own quadrant to smem ----
            if (diag) {
                const int rA = t0 + w16 + qr;
                const int rB = rA + 8;
#pragma unroll
                for (int j = 0; j < 8; ++j) {
                    const int sc = s0 + c64 + 8 * j + qc;
                    if (sc     >= rA) Sacc[j][0] = 0.0f;
                    if (sc + 1 >= rA) Sacc[j][1] = 0.0f;
                    if (sc     >= rB) Sacc[j][2] = 0.0f;
                    if (sc + 1 >= rB) Sacc[j][3] = 0.0f;
                }
            }
            {
                const uint32_t base = sb + SM_S + (uint32_t)wc * 16384u;
                const int r0l = w16 + qr;
                const int r1l = r0l + 8;
#pragma unroll
                for (int j = 0; j < 8; ++j) {
                    const int cb = (8 * j + qc) * 2;   // byte col in subtile
                    sts32(base + swz((uint32_t)(r0l * 128 + cb)),
                          pack_h2(Sacc[j][0], Sacc[j][1]));
                    sts32(base + swz((uint32_t)(r1l * 128 + cb)),
                          pack_h2(Sacc[j][2], Sacc[j][3]));
                }
            }
            __syncthreads();

            // ---- stage 2: O[16 rows, own d-half] += S @ V^T ----
#pragma unroll
            for (int jj = 0; jj < 8; ++jj) {
                if (diag && jj > wr) continue;          // all-zero S k-blocks
                const int kb = (jj & 3) * 32 + lgrp * 16;
                const uint32_t tS = sb + SM_S + (uint32_t)((jj >> 2) * 16384);
                const uint32_t tV = sb + SM_V + (uint32_t)((jj >> 2) * 16384);
                uint32_t a0, a1, a2, a3;
                ldsm4(a0, a1, a2, a3,
                      tS + swz((uint32_t)((w16 + lrow) * 128 + kb)));
#pragma unroll
                for (int dg = 0; dg < 4; ++dg) {
                    uint32_t r0, r1, r2, r3;
                    ldsm4(r0, r1, r2, r3,
                          tV + swz((uint32_t)((c64 + dg * 16 + lrow) * 128 + kb)));
                    mma_fp16(Oacc[2 * dg],     a0, a1, a2, a3, r0, r2);
                    mma_fp16(Oacc[2 * dg + 1], a0, a1, a2, a3, r1, r3);
                }
            }
            // no barrier needed here: next S writes occur only after the 8
            // chunk barriers of the next s-tile's stage 1
        }

        // ---- O writeback for this t-tile ----
        const int rA = t0 + w16 + qr;
        const int rB = rA + 8;
#pragma unroll
        for (int j = 0; j < 8; ++j) {
            const int d = c64 + 8 * j + qc;
            *(float2*)(Ob + (size_t)rA * D_ + d) = make_float2(Oacc[j][0], Oacc[j][1]);
            *(float2*)(Ob + (size_t)rB * D_ + d) = make_float2(Oacc[j][2], Oacc[j][3]);
        }
    }
}

// ---------------------------------------------------------------------------
extern "C" void kernel_launch(void* const* d_in, const int* in_sizes, int n_in,
                              void* d_out, int out_size) {
    const float* Q = (const float*)d_in[0];
    const float* V = (const float*)d_in[2];   // d_in[1] is K == Q
    float* O = (float*)d_out;

    prep_kernel<<<NB_ROPE + NB_VT, PTH>>>(Q, V);

    cudaFuncSetAttribute(attn_mma_kernel,
                         cudaFuncAttributeMaxDynamicSharedMemorySize, SM_TOT);
    attn_mma_kernel<<<9 * BH, NTH, SM_TOT>>>(O);
}

// round 13
// speedup vs baseline: 1.3641x; 1.3641x over previous
#include <cuda_runtime.h>
#include <cuda_fp16.h>
#include <cstdint>

#define BH   16
#define T_   2048
#define N_   1024
#define D_   128
#define TM   64           // t-rows per CTA tile
#define TSN  128          // s-cols per CTA tile
#define KC   64           // k-chunk (fp16 elems)
#define NCH  16           // N_/KC
#define NTH  256
#define PTH  256
#define NCPB 17           // CTAs per bh (balanced bins of 16 half-steps)

#define NB_ROPE 32768     // rope part: BH*T_*(N_/4) / 256
#define NB_VT   4096      // vt part:   (T_/32)*(D_/32)*BH

// ---------------- global scratch (static device alloc — allowed) ----------
__device__ __half g_QH[(size_t)BH * T_ * N_];   // 64 MiB (RoPE'd Q, fp16)
__device__ __half g_VTH[(size_t)BH * D_ * T_];  //  8 MiB (V^T, fp16)

// balanced pairing of 64-row t-tiles: cost(tt) = tt/2+1, every bin sums to 16
__constant__ int8_t c_tts[NCPB][2] = {
    {31,-1},{30,-1},{29,1},{28,0},{27,3},{26,2},{25,5},{24,4},
    {23,7},{22,6},{21,9},{20,8},{19,11},{18,10},{17,13},{16,12},{15,14}};

// ---------------- helpers --------------------------------------------------
__device__ __forceinline__ uint32_t smem_u32(const void* p) {
    uint32_t a;
    asm("{ .reg .u64 t; cvta.to.shared.u64 t, %1; cvt.u32.u64 %0, t; }"
        : "=r"(a) : "l"(p));
    return a;
}
__device__ __forceinline__ uint32_t swz(uint32_t off) {   // SW128 swizzle
    return off ^ ((off >> 3) & 0x70);
}
__device__ __forceinline__ void cp16(uint32_t sdst, const void* g) {
    asm volatile("cp.async.cg.shared.global [%0], [%1], 16;\n"
                 :: "r"(sdst), "l"(g) : "memory");
}
#define CP_COMMIT() asm volatile("cp.async.commit_group;\n" ::: "memory")
#define CP_WAIT0()  asm volatile("cp.async.wait_group 0;\n" ::: "memory")

__device__ __forceinline__ void ldsm4(uint32_t& r0, uint32_t& r1,
                                      uint32_t& r2, uint32_t& r3, uint32_t a) {
    asm volatile("ldmatrix.sync.aligned.m8n8.x4.shared.b16 {%0,%1,%2,%3}, [%4];"
                 : "=r"(r0), "=r"(r1), "=r"(r2), "=r"(r3) : "r"(a));
}
__device__ __forceinline__ void mma_fp16(float c[4],
        uint32_t a0, uint32_t a1, uint32_t a2, uint32_t a3,
        uint32_t b0, uint32_t b1) {
    asm volatile(
        "mma.sync.aligned.m16n8k16.row.col.f32.f16.f16.f32 "
        "{%0,%1,%2,%3}, {%4,%5,%6,%7}, {%8,%9}, {%0,%1,%2,%3};"
        : "+f"(c[0]), "+f"(c[1]), "+f"(c[2]), "+f"(c[3])
        : "r"(a0), "r"(a1), "r"(a2), "r"(a3), "r"(b0), "r"(b1));
}
__device__ __forceinline__ void sts32(uint32_t addr, uint32_t v) {
    asm volatile("st.shared.b32 [%0], %1;" :: "r"(addr), "r"(v) : "memory");
}
__device__ __forceinline__ uint32_t pack_h2(float lo, float hi) {
    __half2 h = __floats2half2_rn(lo, hi);
    return *reinterpret_cast<uint32_t*>(&h);
}

// ---------------- merged prep: RoPE (rope blocks) + V^T (vt blocks) -------
__global__ void prep_kernel(const float* __restrict__ Q,
                            const float* __restrict__ V) {
    __shared__ float tile[32][33];
    const uint32_t bid = blockIdx.x;
    const int tid = threadIdx.x;

    if (bid < NB_ROPE) {
        uint32_t i4 = bid * PTH + tid;
        uint32_t p0 = 2u * i4;
        uint32_t n2 = p0 & 511u;
        uint32_t t  = (p0 >> 9) & 2047u;

        const float4 q = ((const float4*)Q)[i4];
        float tf = (float)t;

        float pos0 = (float)(2u * n2);
        float f0 = exp2f(-16.0f * pos0 * (1.0f / (float)N_)) * 0.15915494309189535f;
        float r0 = tf * f0;
        float ph0 = (r0 - floorf(r0)) * 6.283185307179586f;
        float s0, c0; __sincosf(ph0, &s0, &c0);

        float pos1 = (float)(2u * (n2 + 1u));
        float f1 = exp2f(-16.0f * pos1 * (1.0f / (float)N_)) * 0.15915494309189535f;
        float r1 = tf * f1;
        float ph1 = (r1 - floorf(r1)) * 6.283185307179586f;
        float s1, c1; __sincosf(ph1, &s1, &c1);

        uint2 o;
        o.x = pack_h2(q.x * c0 - q.y * s0, q.y * c0 + q.x * s0);
        o.y = pack_h2(q.z * c1 - q.w * s1, q.w * c1 + q.z * s1);
        ((uint2*)g_QH)[i4] = o;
    } else {
        const uint32_t vb = bid - NB_ROPE;
        const int t0 = (int)(vb & 63u) * 32;
        const int d0 = (int)((vb >> 6) & 3u) * 32;
        const int bh = (int)(vb >> 8);
        const int tx = tid & 31, ty = tid >> 5;

        const float* Vb = V + ((size_t)bh * T_) * D_;
#pragma unroll
        for (int i = 0; i < 4; ++i)
            tile[ty + i * 8][tx] = Vb[(size_t)(t0 + ty + i * 8) * D_ + d0 + tx];
        __syncthreads();

        __half* VTb = g_VTH + (size_t)bh * D_ * T_;
#pragma unroll
        for (int i = 0; i < 4; ++i)
            VTb[(size_t)(d0 + ty + i * 8) * T_ + t0 + tx] =
                __float2half(tile[tx][ty + i * 8]);
    }
}

// ---------------- attention (mma.sync fp16, 64x128 tile, 2 CTAs/SM) -------
// smem map (bytes):
//   [0, 48K)   : Q chunk double buffer, buf b at b*24576:
//                Qt [64 r][64 k] (+0, 8K), Qs [128 r][64 k] (+8K, 16K), SW128
//   [48K, 80K) : V tile: V_sub0(+0) V_sub1(+16K), [128 d][64 s] each
//   [80K, 96K) : S tile: S_sub0(+0) S_sub1(+8K),  [64 t][64 s] each
#define SM_V   49152
#define SM_S   81920
#define SM_TOT 98304

__device__ __forceinline__ void load_q_chunk(
    uint32_t sb, int buf, int k0, int t0, int s0, int tid,
    const __half* QHb) {
    uint32_t qb = sb + (uint32_t)buf * 24576u;
    const __half* qt = QHb + (size_t)t0 * N_ + k0;
    const __half* qs = QHb + (size_t)s0 * N_ + k0;
#pragma unroll
    for (int i = 0; i < 2; ++i) {            // Qt: 512 16B units
        int u = tid * 2 + i;
        int r = u >> 3, c = u & 7;
        cp16(qb + swz((uint32_t)(r * 128 + c * 16)), qt + (size_t)r * N_ + c * 8);
    }
#pragma unroll
    for (int i = 0; i < 4; ++i) {            // Qs: 1024 16B units
        int u = tid * 4 + i;
        int r = u >> 3, c = u & 7;
        cp16(qb + 8192u + swz((uint32_t)(r * 128 + c * 16)),
             qs + (size_t)r * N_ + c * 8);
    }
}

__device__ __forceinline__ void load_v_tile(
    uint32_t sb, int s0, int tid, const __half* VHb) {
#pragma unroll
    for (int i = 0; i < 8; ++i) {            // 2048 16B units
        int u = tid * 8 + i;
        int sub = u >> 10, uu = u & 1023;
        int r = uu >> 3, c = uu & 7;
        cp16(sb + SM_V + (uint32_t)sub * 16384u +
                 swz((uint32_t)(r * 128 + c * 16)),
             VHb + (size_t)r * T_ + s0 + sub * 64 + c * 8);
    }
}

__global__ void __launch_bounds__(NTH, 2)
attn_mma_kernel(float* __restrict__ O) {
    extern __shared__ char smem[];
    uint32_t sb = smem_u32(smem);
    const int tid  = threadIdx.x;
    const int w    = tid >> 5;
    const int wm   = w & 3;           // row group: t-rows [16wm, 16wm+16)
    const int wn   = w >> 2;          // col half: s/d cols [64wn, 64wn+64)
    const int lane = tid & 31;
    const int lrow = lane & 15;
    const int lgrp = lane >> 4;
    const int qr   = lane >> 2;
    const int qc   = (lane & 3) << 1;

    const int bh = blockIdx.x / NCPB;
    const int c  = blockIdx.x % NCPB;

    const int ta = c_tts[c][0];
    const int tb = c_tts[c][1];
    const int nrep = (tb >= 0) ? 2 : 1;
    int tts[2]; tts[0] = ta; tts[1] = (tb >= 0) ? tb : ta;

    const __half* QHb = g_QH  + (size_t)bh * T_ * N_;
    const __half* VHb = g_VTH + (size_t)bh * D_ * T_;
    float* Ob = O + (size_t)bh * T_ * D_;

    const int w16 = wm * 16;
    const int c64 = wn * 64;

    // prologue: chunk0 of first s-tile into buf0
    load_q_chunk(sb, 0, 0, tts[0] * TM, 0, tid, QHb);
    CP_COMMIT();

    for (int rep = 0; rep < nrep; ++rep) {
        const int tt = tts[rep];
        const int t0r = tt * TM;
        const int ns  = (tt >> 1) + 1;        // causal s-tiles (128-wide)
        const int roff = (tt & 1) * 64;       // row offset within diag block

        float Oacc[8][4];                     // 16 rows x 64 d (own half)
#pragma unroll
        for (int b = 0; b < 8; ++b)
#pragma unroll
            for (int x = 0; x < 4; ++x) Oacc[b][x] = 0.0f;

        for (int st = 0; st < ns; ++st) {
            const int s0 = st * TSN;
            const bool diag = (st == ns - 1);
            const bool wskip = diag && (c64 >= roff + w16 + 15);

            float Sacc[8][4];                 // 16 rows x 64 s (own half)
#pragma unroll
            for (int b = 0; b < 8; ++b)
#pragma unroll
                for (int x = 0; x < 4; ++x) Sacc[b][x] = 0.0f;

            // ---- stage 1: S = Qt @ Qs^T, 16 double-buffered K=64 chunks --
            for (int cc = 0; cc < NCH; ++cc) {
                CP_WAIT0();
                __syncthreads();
                // issue next loads AFTER the barrier (WAR-safe)
                if (cc + 1 < NCH) {
                    load_q_chunk(sb, (cc + 1) & 1, (cc + 1) * KC, t0r, s0, tid, QHb);
                } else if (st + 1 < ns) {
                    load_q_chunk(sb, 0, 0, t0r, s0 + TSN, tid, QHb);
                } else if (rep + 1 < nrep) {
                    load_q_chunk(sb, 0, 0, tts[rep + 1] * TM, 0, tid, QHb);
                }
                if (cc == 0) load_v_tile(sb, s0, tid, VHb);
                CP_COMMIT();

                if (!wskip) {
                    const uint32_t qb = sb + (uint32_t)(cc & 1) * 24576u;
#pragma unroll
                    for (int ks = 0; ks < 4; ++ks) {
                        const int kb = ks * 32 + lgrp * 16;
                        uint32_t a0, a1, a2, a3;
                        ldsm4(a0, a1, a2, a3,
                              qb + swz((uint32_t)((w16 + lrow) * 128 + kb)));
#pragma unroll
                        for (int sg = 0; sg < 4; ++sg) {
                            if (diag && (c64 + sg * 16 >= roff + w16 + 15)) continue;
                            uint32_t r0, r1, r2, r3;
                            ldsm4(r0, r1, r2, r3,
                                  qb + 8192u +
                                  swz((uint32_t)((c64 + sg * 16 + lrow) * 128 + kb)));
                            mma_fp16(Sacc[2 * sg],     a0, a1, a2, a3, r0, r2);
                            mma_fp16(Sacc[2 * sg + 1], a0, a1, a2, a3, r1, r3);
                        }
                    }
                }
            }

            // ---- mask + fp16-pack S, write own quadrant to smem ----
            if (diag) {
                const int rA = roff + w16 + qr;   // masked when col >= roff+row
                const int rB = rA + 8;
#pragma unroll
                for (int j = 0; j < 8; ++j) {
                    const int sc = c64 + 8 * j + qc;
                    if (sc     >= rA) Sacc[j][0] = 0.0f;
                    if (sc + 1 >= rA) Sacc[j][1] = 0.0f;
                    if (sc     >= rB) Sacc[j][2] = 0.0f;
                    if (sc + 1 >= rB) Sacc[j][3] = 0.0f;
                }
            }
            {
                const uint32_t base = sb + SM_S + (uint32_t)wn * 8192u;
                const int r0l = w16 + qr;
                const int r1l = r0l + 8;
#pragma unroll
                for (int j = 0; j < 8; ++j) {
                    const int cb = (8 * j + qc) * 2;
                    sts32(base + swz((uint32_t)(r0l * 128 + cb)),
                          pack_h2(Sacc[j][0], Sacc[j][1]));
                    sts32(base + swz((uint32_t)(r1l * 128 + cb)),
                          pack_h2(Sacc[j][2], Sacc[j][3]));
                }
            }
            __syncthreads();

            // ---- stage 2: O[16 rows, own d-half] += S @ V^T ----
#pragma unroll
            for (int jj = 0; jj < 8; ++jj) {
                if (diag && (jj * 16 >= roff + 64)) continue;  // all-zero S cols
                const int kb = (jj & 3) * 32 + lgrp * 16;
                const uint32_t tS = sb + SM_S + (uint32_t)((jj >> 2) * 8192);
                const uint32_t tV = sb + SM_V + (uint32_t)((jj >> 2) * 16384);
                uint32_t a0, a1, a2, a3;
                ldsm4(a0, a1, a2, a3,
                      tS + swz((uint32_t)((w16 + lrow) * 128 + kb)));
#pragma unroll
                for (int dg = 0; dg < 4; ++dg) {
                    uint32_t r0, r1, r2, r3;
                    ldsm4(r0, r1, r2, r3,
                          tV + swz((uint32_t)((c64 + dg * 16 + lrow) * 128 + kb)));
                    mma_fp16(Oacc[2 * dg],     a0, a1, a2, a3, r0, r2);
                    mma_fp16(Oacc[2 * dg + 1], a0, a1, a2, a3, r1, r3);
                }
            }
            // no barrier: S/V rewritten only after next stage-1's barriers
        }

        // ---- O writeback for this t-tile ----
        const int rA = t0r + w16 + qr;
        const int rB = rA + 8;
#pragma unroll
        for (int j = 0; j < 8; ++j) {
            const int d = c64 + 8 * j + qc;
            *(float2*)(Ob + (size_t)rA * D_ + d) = make_float2(Oacc[j][0], Oacc[j][1]);
            *(float2*)(Ob + (size_t)rB * D_ + d) = make_float2(Oacc[j][2], Oacc[j][3]);
        }
    }
}

// ---------------------------------------------------------------------------
extern "C" void kernel_launch(void* const* d_in, const int* in_sizes, int n_in,
                              void* d_out, int out_size) {
    const float* Q = (const float*)d_in[0];
    const float* V = (const float*)d_in[2];   // d_in[1] is K == Q
    float* O = (float*)d_out;

    prep_kernel<<<NB_ROPE + NB_VT, PTH>>>(Q, V);

    cudaFuncSetAttribute(attn_mma_kernel,
                         cudaFuncAttributeMaxDynamicSharedMemorySize, SM_TOT);
    attn_mma_kernel<<<NCPB * BH, NTH, SM_TOT>>>(O);
}